// round 14
// baseline (speedup 1.0000x reference)
#include <cuda_runtime.h>

#define BATCH 128
#define VOCAB 128000

// Scratch (no allocation allowed): packed (ordered_key<<32 | ~idx) per row.
__device__ unsigned long long g_best[BATCH];

__device__ __forceinline__ unsigned long long pack_key(float key, unsigned idx) {
    unsigned b = __float_as_uint(key);
    b = (b & 0x80000000u) ? ~b : (b | 0x80000000u);  // order-preserving float->u32
    return ((unsigned long long)b << 32) | (unsigned long long)(~idx); // ties: min idx
}

__global__ void init_kernel() {
    if (threadIdx.x < BATCH) g_best[threadIdx.x] = 0ULL;
}

__device__ __forceinline__ void tf_round(unsigned &x0, unsigned &x1, int r) {
    x0 += x1;
    x1 = __funnelshift_l(x1, x1, r);  // rotl
    x1 ^= x0;
}

// JAX partitionable threefry, 32-bit width:
//   bits1, bits2 = threefry2x32_p.bind(k1, k2, counts_hi, counts_lo)
//   return bits1 ^ bits2                      <-- the 32-bit extraction
// key = (0, 42), counts = iota64 -> (hi=0, lo=j).
// Core verified against Random123 KAT: (0,0)x(0,0) -> 6B200159, 99BA4EFE.
__device__ __forceinline__ unsigned threefry_bits(unsigned j) {
    const unsigned ks0 = 0u;
    const unsigned ks1 = 42u;
    const unsigned ks2 = 0x1BD11BDAu ^ 0u ^ 42u;
    unsigned x0 = 0u + ks0;   // counts_hi = 0
    unsigned x1 = j + ks1;    // counts_lo = j

    tf_round(x0, x1, 13); tf_round(x0, x1, 15); tf_round(x0, x1, 26); tf_round(x0, x1, 6);
    x0 += ks1; x1 += ks2 + 1u;
    tf_round(x0, x1, 17); tf_round(x0, x1, 29); tf_round(x0, x1, 16); tf_round(x0, x1, 24);
    x0 += ks2; x1 += ks0 + 2u;
    tf_round(x0, x1, 13); tf_round(x0, x1, 15); tf_round(x0, x1, 26); tf_round(x0, x1, 6);
    x0 += ks0; x1 += ks1 + 3u;
    tf_round(x0, x1, 17); tf_round(x0, x1, 29); tf_round(x0, x1, 16); tf_round(x0, x1, 24);
    x0 += ks1; x1 += ks2 + 4u;
    tf_round(x0, x1, 13); tf_round(x0, x1, 15); tf_round(x0, x1, 26); tf_round(x0, x1, 6);
    x0 += ks2; x1 += ks0 + 5u;

    return x0 ^ x1;   // bits1 ^ bits2
}

// -ln(e), e = -log1p(-u), u = bitcast((bits>>9)|0x3f800000) - 1.
// Two-branch scheme, ~5e-6 absolute accuracy in the key.
// u == 0 -> e = 0 -> +inf key (matches reference prob/0 = inf).
__device__ __forceinline__ float neg_ln_noise(unsigned bits) {
    float f = __uint_as_float((bits >> 9) | 0x3f800000u);  // [1, 2)
    float u = f - 1.0f;       // exact
    float w = 2.0f - f;       // exact == 1 - u (Sterbenz)

    float t = fmaf(u, 0.2f, 0.25f);
    t = fmaf(u, t, 0.333333333f);
    t = fmaf(u, t, 0.5f);
    t = fmaf(u, t, 1.0f);
    float ep = u * t;                  // series, u < 0.125
    float em = -__logf(w);             // MUFU path otherwise
    float e = (u < 0.125f) ? ep : em;

    return -0.69314718056f * __log2f(e);
}

// Grid: (VOCAB/(256*4*ITERS), BATCH). One row per blockIdx.y.
template <int ITERS>
__global__ void __launch_bounds__(256)
sampler_kernel(const float* __restrict__ logits, const float* __restrict__ temps) {
    const int row = blockIdx.y;
    const float invT = 1.0f / temps[row];
    const float4* L = (const float4*)(logits + (size_t)row * VOCAB);

    const int vec_base = blockIdx.x * (blockDim.x * ITERS);

    float bestK = -__int_as_float(0x7f800000);  // -inf
    unsigned bestI = 0;

    #pragma unroll
    for (int it = 0; it < ITERS; ++it) {
        const int c4 = vec_base + it * blockDim.x + threadIdx.x;
        const unsigned c = (unsigned)c4 * 4u;
        const float4 a = L[c4];
        const unsigned jbase = (unsigned)row * (unsigned)VOCAB + c;

        float v[4] = {a.x, a.y, a.z, a.w};
        #pragma unroll
        for (int q = 0; q < 4; ++q) {
            const unsigned bits = threefry_bits(jbase + (unsigned)q);
            const float k = fmaf(v[q], invT, neg_ln_noise(bits));
            if (k > bestK) { bestK = k; bestI = c + (unsigned)q; }
        }
    }

    __shared__ unsigned long long sbest;
    if (threadIdx.x == 0) sbest = 0ULL;
    __syncthreads();
    atomicMax(&sbest, pack_key(bestK, bestI));
    __syncthreads();
    if (threadIdx.x == 0) atomicMax(&g_best[row], sbest);
}

// float32 output: indices < 2^24 exactly representable -> rel_err can reach 0.
__global__ void finalize_kernel(float* __restrict__ out) {
    const int t = threadIdx.x;
    if (t < BATCH) {
        unsigned idx = ~(unsigned)(g_best[t] & 0xFFFFFFFFu);
        out[t] = (float)idx;
    }
}

extern "C" void kernel_launch(void* const* d_in, const int* in_sizes, int n_in,
                              void* d_out, int out_size) {
    const float* logits = (const float*)d_in[0];
    const float* temps  = (const float*)d_in[1];
    if (n_in >= 2 && in_sizes[0] == BATCH && in_sizes[1] == BATCH * VOCAB) {
        logits = (const float*)d_in[1];
        temps  = (const float*)d_in[0];
    }

    init_kernel<<<1, 128>>>();

    constexpr int ITERS = 5;  // 256 thr * 4 * 5 = 5120 cols/block; 128000/5120 = 25
    dim3 grid(VOCAB / (256 * 4 * ITERS), BATCH);
    sampler_kernel<ITERS><<<grid, 256>>>(logits, temps);

    finalize_kernel<<<1, 128>>>((float*)d_out);
}

// round 15
// speedup vs baseline: 1.0072x; 1.0072x over previous
#include <cuda_runtime.h>

#define BATCH 128
#define VOCAB 128000
#define XBLOCKS 25   /* VOCAB / (256*4*5) */

// Per-(row, block) partial results: packed (ordered_key<<32 | ~idx).
// Every slot is overwritten on every launch -> no init pass, no atomics,
// graph-replay deterministic.
__device__ unsigned long long g_part[BATCH * XBLOCKS];

__device__ __forceinline__ unsigned long long pack_key(float key, unsigned idx) {
    unsigned b = __float_as_uint(key);
    b = (b & 0x80000000u) ? ~b : (b | 0x80000000u);  // order-preserving float->u32
    return ((unsigned long long)b << 32) | (unsigned long long)(~idx); // ties: min idx
}

__device__ __forceinline__ void tf_round(unsigned &x0, unsigned &x1, int r) {
    x0 += x1;
    x1 = __funnelshift_l(x1, x1, r);  // rotl
    x1 ^= x0;
}

// JAX partitionable threefry, 32-bit width (CONFIRMED R14, rel_err = 0):
//   bits = out0 ^ out1 of threefry2x32(key=(0,42), counter=(hi=0, lo=j))
__device__ __forceinline__ unsigned threefry_bits(unsigned j) {
    const unsigned ks0 = 0u;
    const unsigned ks1 = 42u;
    const unsigned ks2 = 0x1BD11BDAu ^ 0u ^ 42u;
    unsigned x0 = 0u + ks0;
    unsigned x1 = j + ks1;

    tf_round(x0, x1, 13); tf_round(x0, x1, 15); tf_round(x0, x1, 26); tf_round(x0, x1, 6);
    x0 += ks1; x1 += ks2 + 1u;
    tf_round(x0, x1, 17); tf_round(x0, x1, 29); tf_round(x0, x1, 16); tf_round(x0, x1, 24);
    x0 += ks2; x1 += ks0 + 2u;
    tf_round(x0, x1, 13); tf_round(x0, x1, 15); tf_round(x0, x1, 26); tf_round(x0, x1, 6);
    x0 += ks0; x1 += ks1 + 3u;
    tf_round(x0, x1, 17); tf_round(x0, x1, 29); tf_round(x0, x1, 16); tf_round(x0, x1, 24);
    x0 += ks1; x1 += ks2 + 4u;
    tf_round(x0, x1, 13); tf_round(x0, x1, 15); tf_round(x0, x1, 26); tf_round(x0, x1, 6);
    x0 += ks2; x1 += ks0 + 5u;

    return x0 ^ x1;
}

// -ln(e), e = -log1p(-u), u = bitcast((bits>>9)|0x3f800000) - 1.
// Two-branch scheme, ~5e-6 absolute accuracy in the key.
// u == 0 -> e = 0 -> +inf key (matches reference prob/0 = inf).
__device__ __forceinline__ float neg_ln_noise(unsigned bits) {
    float f = __uint_as_float((bits >> 9) | 0x3f800000u);  // [1, 2)
    float u = f - 1.0f;       // exact
    float w = 2.0f - f;       // exact == 1 - u (Sterbenz)

    float t = fmaf(u, 0.2f, 0.25f);
    t = fmaf(u, t, 0.333333333f);
    t = fmaf(u, t, 0.5f);
    t = fmaf(u, t, 1.0f);
    float ep = u * t;                  // series, u < 0.125
    float em = -__logf(w);             // MUFU path otherwise
    float e = (u < 0.125f) ? ep : em;

    return -0.69314718056f * __log2f(e);
}

// Grid: (XBLOCKS, BATCH), 256 threads, 20 elements/thread.
template <int ITERS>
__global__ void __launch_bounds__(256)
sampler_kernel(const float* __restrict__ logits, const float* __restrict__ temps) {
    const int row = blockIdx.y;
    const float invT = 1.0f / temps[row];
    const float4* L = (const float4*)(logits + (size_t)row * VOCAB);

    const int vec_base = blockIdx.x * (blockDim.x * ITERS);

    float bestK = -__int_as_float(0x7f800000);  // -inf
    unsigned bestI = 0;

    #pragma unroll
    for (int it = 0; it < ITERS; ++it) {
        const int c4 = vec_base + it * blockDim.x + threadIdx.x;
        const unsigned c = (unsigned)c4 * 4u;
        const float4 a = L[c4];
        const unsigned jbase = (unsigned)row * (unsigned)VOCAB + c;

        float v[4] = {a.x, a.y, a.z, a.w};
        #pragma unroll
        for (int q = 0; q < 4; ++q) {
            const unsigned bits = threefry_bits(jbase + (unsigned)q);
            const float k = fmaf(v[q], invT, neg_ln_noise(bits));
            if (k > bestK) { bestK = k; bestI = c + (unsigned)q; }
        }
    }

    __shared__ unsigned long long sbest;
    if (threadIdx.x == 0) sbest = 0ULL;
    __syncthreads();
    atomicMax(&sbest, pack_key(bestK, bestI));
    __syncthreads();
    if (threadIdx.x == 0) g_part[row * XBLOCKS + blockIdx.x] = sbest;
}

// One warp per row: lanes 0..24 load partials, shuffle-reduce max, write float.
__global__ void __launch_bounds__(32)
finalize_kernel(float* __restrict__ out) {
    const int row = blockIdx.x;
    const int lane = threadIdx.x;
    unsigned long long v = (lane < XBLOCKS) ? g_part[row * XBLOCKS + lane] : 0ULL;
    #pragma unroll
    for (int off = 16; off > 0; off >>= 1) {
        unsigned long long o = __shfl_xor_sync(0xFFFFFFFFu, v, off);
        if (o > v) v = o;
    }
    if (lane == 0) {
        unsigned idx = ~(unsigned)(v & 0xFFFFFFFFu);
        out[row] = (float)idx;
    }
}

extern "C" void kernel_launch(void* const* d_in, const int* in_sizes, int n_in,
                              void* d_out, int out_size) {
    const float* logits = (const float*)d_in[0];
    const float* temps  = (const float*)d_in[1];
    if (n_in >= 2 && in_sizes[0] == BATCH && in_sizes[1] == BATCH * VOCAB) {
        logits = (const float*)d_in[1];
        temps  = (const float*)d_in[0];
    }

    constexpr int ITERS = 5;  // 256 thr * 4 * 5 = 5120 cols/block; 128000/5120 = 25
    dim3 grid(XBLOCKS, BATCH);
    sampler_kernel<ITERS><<<grid, 256>>>(logits, temps);

    finalize_kernel<<<BATCH, 32>>>((float*)d_out);
}

// round 16
// speedup vs baseline: 1.0395x; 1.0321x over previous
#include <cuda_runtime.h>

#define BATCH 128
#define VOCAB 128000
#define XBLOCKS 25   /* VOCAB / (256*4*5) */

// Per-(row, block) partials: packed (ordered_key<<32 | ~idx). Every slot is
// overwritten every launch. Arrival counters return to 0 at the end of every
// launch (last block resets) -> graph-replay deterministic, no init kernel.
__device__ unsigned long long g_part[BATCH * XBLOCKS];
__device__ unsigned int g_count[BATCH];   // zero-init at load; self-resetting

__device__ __forceinline__ unsigned long long pack_key(float key, unsigned idx) {
    unsigned b = __float_as_uint(key);
    b = (b & 0x80000000u) ? ~b : (b | 0x80000000u);  // order-preserving float->u32
    return ((unsigned long long)b << 32) | (unsigned long long)(~idx); // ties: min idx
}

__device__ __forceinline__ void tf_round(unsigned &x0, unsigned &x1, int r) {
    x0 += x1;
    x1 = __funnelshift_l(x1, x1, r);  // rotl
    x1 ^= x0;
}

// JAX partitionable threefry, 32-bit width (CONFIRMED, rel_err = 0):
//   bits = out0 ^ out1 of threefry2x32(key=(0,42), counter=(hi=0, lo=j))
__device__ __forceinline__ unsigned threefry_bits(unsigned j) {
    const unsigned ks0 = 0u;
    const unsigned ks1 = 42u;
    const unsigned ks2 = 0x1BD11BDAu ^ 0u ^ 42u;
    unsigned x0 = 0u + ks0;
    unsigned x1 = j + ks1;

    tf_round(x0, x1, 13); tf_round(x0, x1, 15); tf_round(x0, x1, 26); tf_round(x0, x1, 6);
    x0 += ks1; x1 += ks2 + 1u;
    tf_round(x0, x1, 17); tf_round(x0, x1, 29); tf_round(x0, x1, 16); tf_round(x0, x1, 24);
    x0 += ks2; x1 += ks0 + 2u;
    tf_round(x0, x1, 13); tf_round(x0, x1, 15); tf_round(x0, x1, 26); tf_round(x0, x1, 6);
    x0 += ks0; x1 += ks1 + 3u;
    tf_round(x0, x1, 17); tf_round(x0, x1, 29); tf_round(x0, x1, 16); tf_round(x0, x1, 24);
    x0 += ks1; x1 += ks2 + 4u;
    tf_round(x0, x1, 13); tf_round(x0, x1, 15); tf_round(x0, x1, 26); tf_round(x0, x1, 6);
    x0 += ks2; x1 += ks0 + 5u;

    return x0 ^ x1;
}

// -ln(e), e = -log1p(-u), u = bitcast((bits>>9)|0x3f800000) - 1.
// Two-branch scheme, ~5e-6 absolute accuracy in the key.
// u == 0 -> e = 0 -> +inf key (matches reference prob/0 = inf).
__device__ __forceinline__ float neg_ln_noise(unsigned bits) {
    float f = __uint_as_float((bits >> 9) | 0x3f800000u);  // [1, 2)
    float u = f - 1.0f;       // exact
    float w = 2.0f - f;       // exact == 1 - u (Sterbenz)

    float t = fmaf(u, 0.2f, 0.25f);
    t = fmaf(u, t, 0.333333333f);
    t = fmaf(u, t, 0.5f);
    t = fmaf(u, t, 1.0f);
    float ep = u * t;                  // series, u < 0.125
    float em = -__logf(w);             // MUFU path otherwise
    float e = (u < 0.125f) ? ep : em;

    return -0.69314718056f * __log2f(e);
}

__device__ __forceinline__ unsigned long long warp_max(unsigned long long v) {
    #pragma unroll
    for (int off = 16; off > 0; off >>= 1) {
        unsigned long long o = __shfl_xor_sync(0xFFFFFFFFu, v, off);
        if (o > v) v = o;
    }
    return v;
}

// Single fused kernel. Grid: (XBLOCKS, BATCH), 256 threads, 20 elems/thread.
// Last-arriving block per row reduces the partials and writes the output.
template <int ITERS>
__global__ void __launch_bounds__(256)
sampler_kernel(const float* __restrict__ logits, const float* __restrict__ temps,
               float* __restrict__ out) {
    const int row = blockIdx.y;
    const float invT = 1.0f / temps[row];
    const float4* L = (const float4*)(logits + (size_t)row * VOCAB);

    const int vec_base = blockIdx.x * (blockDim.x * ITERS);

    float bestK = -__int_as_float(0x7f800000);  // -inf
    unsigned bestI = 0;

    #pragma unroll
    for (int it = 0; it < ITERS; ++it) {
        const int c4 = vec_base + it * blockDim.x + threadIdx.x;
        const unsigned c = (unsigned)c4 * 4u;
        const float4 a = L[c4];
        const unsigned jbase = (unsigned)row * (unsigned)VOCAB + c;

        float v[4] = {a.x, a.y, a.z, a.w};
        #pragma unroll
        for (int q = 0; q < 4; ++q) {
            const unsigned bits = threefry_bits(jbase + (unsigned)q);
            const float k = fmaf(v[q], invT, neg_ln_noise(bits));
            if (k > bestK) { bestK = k; bestI = c + (unsigned)q; }
        }
    }

    // Block reduction: warp shuffle first, then 1 smem atomic per warp.
    __shared__ unsigned long long sbest;
    __shared__ int sdone;
    if (threadIdx.x == 0) { sbest = 0ULL; sdone = 0; }
    __syncthreads();

    unsigned long long p = warp_max(pack_key(bestK, bestI));
    if ((threadIdx.x & 31) == 0) atomicMax(&sbest, p);
    __syncthreads();

    // Publish partial; last arriving block finalizes this row.
    if (threadIdx.x == 0) {
        g_part[row * XBLOCKS + blockIdx.x] = sbest;
        __threadfence();
        unsigned old = atomicAdd(&g_count[row], 1u);
        if (old == XBLOCKS - 1) sdone = 1;
    }
    __syncthreads();

    if (sdone && threadIdx.x < 32) {
        unsigned long long v = (threadIdx.x < XBLOCKS)
                             ? g_part[row * XBLOCKS + threadIdx.x] : 0ULL;
        v = warp_max(v);
        if (threadIdx.x == 0) {
            out[row] = (float)(~(unsigned)(v & 0xFFFFFFFFu));
            g_count[row] = 0;   // reset for next launch / graph replay
        }
    }
}

extern "C" void kernel_launch(void* const* d_in, const int* in_sizes, int n_in,
                              void* d_out, int out_size) {
    const float* logits = (const float*)d_in[0];
    const float* temps  = (const float*)d_in[1];
    if (n_in >= 2 && in_sizes[0] == BATCH && in_sizes[1] == BATCH * VOCAB) {
        logits = (const float*)d_in[1];
        temps  = (const float*)d_in[0];
    }

    constexpr int ITERS = 5;  // 256 thr * 4 * 5 = 5120 cols/block; 128000/5120 = 25
    dim3 grid(XBLOCKS, BATCH);
    sampler_kernel<ITERS><<<grid, 256>>>(logits, temps, (float*)d_out);
}